// round 5
// baseline (speedup 1.0000x reference)
#include <cuda_runtime.h>
#include <mma.h>
#include <math.h>

using namespace nvcuda;

#define EMBED   256
#define PAIRS   15
#define TOKENS  16384         // 32 * 512
#define KPAIR   512           // 2 * EMBED
#define KFINAL  (PAIRS * EMBED)  // 3840

#define BM 128
#define BN 64
#define BK 32
#define LDA (BK + 4)          // 36 floats = 144B (multiple of 16B)
#define LDB (BN + 4)          // 68 floats = 272B (multiple of 16B)
#define NTHREADS 256

// Intermediate H[p][token][d] (fp32). ~252 MB static device array (allocation-free).
__device__ float g_H[(size_t)PAIRS * TOKENS * EMBED];

// triu_indices(6, k=1) order
__constant__ int c_PI[PAIRS] = {0,0,0,0,0,1,1,1,1,2,2,2,3,3,4};
__constant__ int c_PJ[PAIRS] = {1,2,3,4,5,2,3,4,5,3,4,5,4,5,5};

// ---------------------------------------------------------------------------
// Kernel 1: per-pair GEMM  H[p] = tanh(concat(F_i, F_j) @ W_pair[p] + b_pair[p]) * mask
// Tiles: CTA = 128x64, 8 warps (4x2), warp = 32x32 = 2x2 wmma m16n16k8 tf32.
// Masked pairs: CTA exits immediately (kernel 2 never reads those regions).
// ---------------------------------------------------------------------------
__global__ void __launch_bounds__(NTHREADS)
pair_gemm_kernel(const float* __restrict__ features,
                 const float* __restrict__ W_pair,
                 const float* __restrict__ b_pair,
                 const int*   __restrict__ NAS)
{
    __shared__ float smem[BM * BN];       // 32 KB; holds A+B tiles (6784 fl), then C tile
    float* As = smem;                      // [BM][LDA]
    float* Bs = smem + BM * LDA;           // [BK][LDB]

    const int p    = blockIdx.z;
    const int tok0 = blockIdx.x * BM;
    const int n0   = blockIdx.y * BN;
    const int tid  = threadIdx.x;
    const int warp = tid >> 5;
    const int wm   = warp & 3;             // 0..3  (M direction)
    const int wn   = warp >> 2;            // 0..1  (N direction)

    const int fi = c_PI[p], fj = c_PJ[p];
    const int ni = (fi < 2) ? 1 : NAS[fi];
    const int nj = (fj < 2) ? 1 : NAS[fj];
    const float mask = (float)(ni * nj);
    if (mask == 0.0f) return;              // inactive pair: contributes nothing downstream

    const float* featI = features + ((size_t)fi * TOKENS + tok0) * EMBED;
    const float* featJ = features + ((size_t)fj * TOKENS + tok0) * EMBED;
    const float* Wp    = W_pair   + (size_t)p * KPAIR * EMBED + n0;
    float*       Hout  = g_H      + ((size_t)p * TOKENS + tok0) * EMBED + n0;

    wmma::fragment<wmma::accumulator, 16, 16, 8, float> cf[2][2];
    #pragma unroll
    for (int a = 0; a < 2; a++)
        #pragma unroll
        for (int b = 0; b < 2; b++)
            wmma::fill_fragment(cf[a][b], 0.0f);

    for (int k0 = 0; k0 < KPAIR; k0 += BK) {
        // A-tile source: first 256 k's come from F_i, next 256 from F_j
        const float* Asrc = (k0 < EMBED) ? (featI + k0) : (featJ + (k0 - EMBED));

        // Load A tile: 128x32 floats = 1024 float4, 4 per thread
        #pragma unroll
        for (int t = 0; t < 4; t++) {
            int q   = tid + t * NTHREADS;
            int row = q >> 3, c4 = q & 7;
            float4 v = *reinterpret_cast<const float4*>(Asrc + (size_t)row * EMBED + c4 * 4);
            float* d = As + row * LDA + c4 * 4;
            d[0] = wmma::__float_to_tf32(v.x);
            d[1] = wmma::__float_to_tf32(v.y);
            d[2] = wmma::__float_to_tf32(v.z);
            d[3] = wmma::__float_to_tf32(v.w);
        }
        // Load B tile: 32x64 floats = 512 float4, 2 per thread
        #pragma unroll
        for (int t = 0; t < 2; t++) {
            int q   = tid + t * NTHREADS;
            int row = q >> 4, c4 = q & 15;
            float4 v = *reinterpret_cast<const float4*>(Wp + (size_t)(k0 + row) * EMBED + c4 * 4);
            float* d = Bs + row * LDB + c4 * 4;
            d[0] = wmma::__float_to_tf32(v.x);
            d[1] = wmma::__float_to_tf32(v.y);
            d[2] = wmma::__float_to_tf32(v.z);
            d[3] = wmma::__float_to_tf32(v.w);
        }
        __syncthreads();

        #pragma unroll
        for (int kk = 0; kk < BK; kk += 8) {
            wmma::fragment<wmma::matrix_a, 16, 16, 8, wmma::precision::tf32, wmma::row_major> af[2];
            wmma::fragment<wmma::matrix_b, 16, 16, 8, wmma::precision::tf32, wmma::row_major> bf[2];
            wmma::load_matrix_sync(af[0], As + (wm * 32 +  0) * LDA + kk, LDA);
            wmma::load_matrix_sync(af[1], As + (wm * 32 + 16) * LDA + kk, LDA);
            wmma::load_matrix_sync(bf[0], Bs + kk * LDB + wn * 32 +  0, LDB);
            wmma::load_matrix_sync(bf[1], Bs + kk * LDB + wn * 32 + 16, LDB);
            #pragma unroll
            for (int a = 0; a < 2; a++)
                #pragma unroll
                for (int b = 0; b < 2; b++)
                    wmma::mma_sync(cf[a][b], af[a], bf[b], cf[a][b]);
        }
        __syncthreads();
    }

    // Epilogue: stage C in smem, then bias + tanh + mask, coalesced float4 writes
    #pragma unroll
    for (int a = 0; a < 2; a++)
        #pragma unroll
        for (int b = 0; b < 2; b++)
            wmma::store_matrix_sync(smem + (wm * 32 + a * 16) * BN + wn * 32 + b * 16,
                                    cf[a][b], BN, wmma::mem_row_major);
    __syncthreads();

    const float* bp = b_pair + p * EMBED + n0;
    for (int q = tid; q < BM * BN / 4; q += NTHREADS) {
        int row = q >> 4, c4 = q & 15;
        float4 v  = *reinterpret_cast<float4*>(smem + row * BN + c4 * 4);
        float4 bb = *reinterpret_cast<const float4*>(bp + c4 * 4);
        float4 o;
        o.x = tanhf(v.x + bb.x) * mask;
        o.y = tanhf(v.y + bb.y) * mask;
        o.z = tanhf(v.z + bb.z) * mask;
        o.w = tanhf(v.w + bb.w) * mask;
        *reinterpret_cast<float4*>(Hout + (size_t)row * EMBED + c4 * 4) = o;
    }
}

// ---------------------------------------------------------------------------
// Kernel 2: out = H_flat @ W_final + b_final   (M=16384, K=3840, N=256)
// K-tiles belonging to masked pairs are skipped entirely (exact zeros).
// ---------------------------------------------------------------------------
__global__ void __launch_bounds__(NTHREADS)
final_gemm_kernel(const float* __restrict__ W_final,
                  const float* __restrict__ b_final,
                  const int*   __restrict__ NAS,
                  float*       __restrict__ out)
{
    __shared__ float smem[BM * BN];
    float* As = smem;
    float* Bs = smem + BM * LDA;

    const int tok0 = blockIdx.x * BM;
    const int n0   = blockIdx.y * BN;
    const int tid  = threadIdx.x;
    const int warp = tid >> 5;
    const int wm   = warp & 3;
    const int wn   = warp >> 2;

    // Per-pair active flags (block-uniform; derived from small NAS reads)
    int nas_eff[6];
    #pragma unroll
    for (int f = 0; f < 6; f++) nas_eff[f] = (f < 2) ? 1 : NAS[f];

    wmma::fragment<wmma::accumulator, 16, 16, 8, float> cf[2][2];
    #pragma unroll
    for (int a = 0; a < 2; a++)
        #pragma unroll
        for (int b = 0; b < 2; b++)
            wmma::fill_fragment(cf[a][b], 0.0f);

    for (int k0 = 0; k0 < KFINAL; k0 += BK) {
        const int p = k0 >> 8;                       // pair owning this K-tile
        if (nas_eff[c_PI[p]] * nas_eff[c_PJ[p]] == 0) continue;  // block-uniform skip

        const float* Asrc = g_H + ((size_t)p * TOKENS + tok0) * EMBED + (k0 & (EMBED - 1));

        #pragma unroll
        for (int t = 0; t < 4; t++) {
            int q   = tid + t * NTHREADS;
            int row = q >> 3, c4 = q & 7;
            float4 v = *reinterpret_cast<const float4*>(Asrc + (size_t)row * EMBED + c4 * 4);
            float* d = As + row * LDA + c4 * 4;
            d[0] = wmma::__float_to_tf32(v.x);
            d[1] = wmma::__float_to_tf32(v.y);
            d[2] = wmma::__float_to_tf32(v.z);
            d[3] = wmma::__float_to_tf32(v.w);
        }
        #pragma unroll
        for (int t = 0; t < 2; t++) {
            int q   = tid + t * NTHREADS;
            int row = q >> 4, c4 = q & 15;
            float4 v = *reinterpret_cast<const float4*>(
                W_final + (size_t)(k0 + row) * EMBED + n0 + c4 * 4);
            float* d = Bs + row * LDB + c4 * 4;
            d[0] = wmma::__float_to_tf32(v.x);
            d[1] = wmma::__float_to_tf32(v.y);
            d[2] = wmma::__float_to_tf32(v.z);
            d[3] = wmma::__float_to_tf32(v.w);
        }
        __syncthreads();

        #pragma unroll
        for (int kk = 0; kk < BK; kk += 8) {
            wmma::fragment<wmma::matrix_a, 16, 16, 8, wmma::precision::tf32, wmma::row_major> af[2];
            wmma::fragment<wmma::matrix_b, 16, 16, 8, wmma::precision::tf32, wmma::row_major> bf[2];
            wmma::load_matrix_sync(af[0], As + (wm * 32 +  0) * LDA + kk, LDA);
            wmma::load_matrix_sync(af[1], As + (wm * 32 + 16) * LDA + kk, LDA);
            wmma::load_matrix_sync(bf[0], Bs + kk * LDB + wn * 32 +  0, LDB);
            wmma::load_matrix_sync(bf[1], Bs + kk * LDB + wn * 32 + 16, LDB);
            #pragma unroll
            for (int a = 0; a < 2; a++)
                #pragma unroll
                for (int b = 0; b < 2; b++)
                    wmma::mma_sync(cf[a][b], af[a], bf[b], cf[a][b]);
        }
        __syncthreads();
    }

    #pragma unroll
    for (int a = 0; a < 2; a++)
        #pragma unroll
        for (int b = 0; b < 2; b++)
            wmma::store_matrix_sync(smem + (wm * 32 + a * 16) * BN + wn * 32 + b * 16,
                                    cf[a][b], BN, wmma::mem_row_major);
    __syncthreads();

    const float* bf_ = b_final + n0;
    float* Optr = out + (size_t)tok0 * EMBED + n0;
    for (int q = tid; q < BM * BN / 4; q += NTHREADS) {
        int row = q >> 4, c4 = q & 15;
        float4 v  = *reinterpret_cast<float4*>(smem + row * BN + c4 * 4);
        float4 bb = *reinterpret_cast<const float4*>(bf_ + c4 * 4);
        float4 o;
        o.x = v.x + bb.x;
        o.y = v.y + bb.y;
        o.z = v.z + bb.z;
        o.w = v.w + bb.w;
        *reinterpret_cast<float4*>(Optr + (size_t)row * EMBED + c4 * 4) = o;
    }
}

// ---------------------------------------------------------------------------
extern "C" void kernel_launch(void* const* d_in, const int* in_sizes, int n_in,
                              void* d_out, int out_size)
{
    const float* features = (const float*)d_in[0];
    const float* W_pair   = (const float*)d_in[1];
    const float* b_pair   = (const float*)d_in[2];
    const float* W_final  = (const float*)d_in[3];
    const float* b_final  = (const float*)d_in[4];
    const int*   NAS      = (const int*)  d_in[5];
    float*       out      = (float*)d_out;

    dim3 block(NTHREADS);
    dim3 grid1(TOKENS / BM, EMBED / BN, PAIRS);   // 128 x 4 x 15
    pair_gemm_kernel<<<grid1, block>>>(features, W_pair, b_pair, NAS);

    dim3 grid2(TOKENS / BM, EMBED / BN);          // 128 x 4
    final_gemm_kernel<<<grid2, block>>>(W_final, b_final, NAS, out);
}

// round 6
// speedup vs baseline: 1.0108x; 1.0108x over previous
#include <cuda_runtime.h>
#include <mma.h>
#include <math.h>

using namespace nvcuda;

#define EMBED   256
#define PAIRS   15
#define TOKENS  16384         // 32 * 512
#define KPAIR   512           // 2 * EMBED
#define KFINAL  (PAIRS * EMBED)  // 3840

#define BM 128
#define BN 64
#define BK 32
#define LDA (BK + 4)          // 36 floats = 144B (multiple of 16B)
#define LDB (BN + 4)          // 68 floats = 272B (multiple of 16B)
#define NTHREADS 256

// Intermediate H[p][token][d] (fp32). ~252 MB static device array (allocation-free).
__device__ float g_H[(size_t)PAIRS * TOKENS * EMBED];

// triu_indices(6, k=1) order
__constant__ int c_PI[PAIRS] = {0,0,0,0,0,1,1,1,1,2,2,2,3,3,4};
__constant__ int c_PJ[PAIRS] = {1,2,3,4,5,2,3,4,5,3,4,5,4,5,5};

// ---------------------------------------------------------------------------
// Kernel 1: per-pair GEMM  H[p] = tanh(concat(F_i, F_j) @ W_pair[p] + b_pair[p]) * mask
// Tiles: CTA = 128x64, 8 warps (4x2), warp = 32x32 = 2x2 wmma m16n16k8 tf32.
// Masked pairs: CTA exits immediately (kernel 2 never reads those regions).
// ---------------------------------------------------------------------------
__global__ void __launch_bounds__(NTHREADS)
pair_gemm_kernel(const float* __restrict__ features,
                 const float* __restrict__ W_pair,
                 const float* __restrict__ b_pair,
                 const int*   __restrict__ NAS)
{
    __shared__ float smem[BM * BN];       // 32 KB; holds A+B tiles (6784 fl), then C tile
    float* As = smem;                      // [BM][LDA]
    float* Bs = smem + BM * LDA;           // [BK][LDB]

    const int p    = blockIdx.z;
    const int tok0 = blockIdx.x * BM;
    const int n0   = blockIdx.y * BN;
    const int tid  = threadIdx.x;
    const int warp = tid >> 5;
    const int wm   = warp & 3;             // 0..3  (M direction)
    const int wn   = warp >> 2;            // 0..1  (N direction)

    const int fi = c_PI[p], fj = c_PJ[p];
    const int ni = (fi < 2) ? 1 : NAS[fi];
    const int nj = (fj < 2) ? 1 : NAS[fj];
    const float mask = (float)(ni * nj);
    if (mask == 0.0f) return;              // inactive pair: contributes nothing downstream

    const float* featI = features + ((size_t)fi * TOKENS + tok0) * EMBED;
    const float* featJ = features + ((size_t)fj * TOKENS + tok0) * EMBED;
    const float* Wp    = W_pair   + (size_t)p * KPAIR * EMBED + n0;
    float*       Hout  = g_H      + ((size_t)p * TOKENS + tok0) * EMBED + n0;

    wmma::fragment<wmma::accumulator, 16, 16, 8, float> cf[2][2];
    #pragma unroll
    for (int a = 0; a < 2; a++)
        #pragma unroll
        for (int b = 0; b < 2; b++)
            wmma::fill_fragment(cf[a][b], 0.0f);

    for (int k0 = 0; k0 < KPAIR; k0 += BK) {
        // A-tile source: first 256 k's come from F_i, next 256 from F_j
        const float* Asrc = (k0 < EMBED) ? (featI + k0) : (featJ + (k0 - EMBED));

        // Load A tile: 128x32 floats = 1024 float4, 4 per thread
        #pragma unroll
        for (int t = 0; t < 4; t++) {
            int q   = tid + t * NTHREADS;
            int row = q >> 3, c4 = q & 7;
            float4 v = *reinterpret_cast<const float4*>(Asrc + (size_t)row * EMBED + c4 * 4);
            float* d = As + row * LDA + c4 * 4;
            d[0] = wmma::__float_to_tf32(v.x);
            d[1] = wmma::__float_to_tf32(v.y);
            d[2] = wmma::__float_to_tf32(v.z);
            d[3] = wmma::__float_to_tf32(v.w);
        }
        // Load B tile: 32x64 floats = 512 float4, 2 per thread
        #pragma unroll
        for (int t = 0; t < 2; t++) {
            int q   = tid + t * NTHREADS;
            int row = q >> 4, c4 = q & 15;
            float4 v = *reinterpret_cast<const float4*>(Wp + (size_t)(k0 + row) * EMBED + c4 * 4);
            float* d = Bs + row * LDB + c4 * 4;
            d[0] = wmma::__float_to_tf32(v.x);
            d[1] = wmma::__float_to_tf32(v.y);
            d[2] = wmma::__float_to_tf32(v.z);
            d[3] = wmma::__float_to_tf32(v.w);
        }
        __syncthreads();

        #pragma unroll
        for (int kk = 0; kk < BK; kk += 8) {
            wmma::fragment<wmma::matrix_a, 16, 16, 8, wmma::precision::tf32, wmma::row_major> af[2];
            wmma::fragment<wmma::matrix_b, 16, 16, 8, wmma::precision::tf32, wmma::row_major> bf[2];
            wmma::load_matrix_sync(af[0], As + (wm * 32 +  0) * LDA + kk, LDA);
            wmma::load_matrix_sync(af[1], As + (wm * 32 + 16) * LDA + kk, LDA);
            wmma::load_matrix_sync(bf[0], Bs + kk * LDB + wn * 32 +  0, LDB);
            wmma::load_matrix_sync(bf[1], Bs + kk * LDB + wn * 32 + 16, LDB);
            #pragma unroll
            for (int a = 0; a < 2; a++)
                #pragma unroll
                for (int b = 0; b < 2; b++)
                    wmma::mma_sync(cf[a][b], af[a], bf[b], cf[a][b]);
        }
        __syncthreads();
    }

    // Epilogue: stage C in smem, then bias + tanh + mask, coalesced float4 writes
    #pragma unroll
    for (int a = 0; a < 2; a++)
        #pragma unroll
        for (int b = 0; b < 2; b++)
            wmma::store_matrix_sync(smem + (wm * 32 + a * 16) * BN + wn * 32 + b * 16,
                                    cf[a][b], BN, wmma::mem_row_major);
    __syncthreads();

    const float* bp = b_pair + p * EMBED + n0;
    for (int q = tid; q < BM * BN / 4; q += NTHREADS) {
        int row = q >> 4, c4 = q & 15;
        float4 v  = *reinterpret_cast<float4*>(smem + row * BN + c4 * 4);
        float4 bb = *reinterpret_cast<const float4*>(bp + c4 * 4);
        float4 o;
        o.x = tanhf(v.x + bb.x) * mask;
        o.y = tanhf(v.y + bb.y) * mask;
        o.z = tanhf(v.z + bb.z) * mask;
        o.w = tanhf(v.w + bb.w) * mask;
        *reinterpret_cast<float4*>(Hout + (size_t)row * EMBED + c4 * 4) = o;
    }
}

// ---------------------------------------------------------------------------
// Kernel 2: out = H_flat @ W_final + b_final   (M=16384, K=3840, N=256)
// K-tiles belonging to masked pairs are skipped entirely (exact zeros).
// ---------------------------------------------------------------------------
__global__ void __launch_bounds__(NTHREADS)
final_gemm_kernel(const float* __restrict__ W_final,
                  const float* __restrict__ b_final,
                  const int*   __restrict__ NAS,
                  float*       __restrict__ out)
{
    __shared__ float smem[BM * BN];
    float* As = smem;
    float* Bs = smem + BM * LDA;

    const int tok0 = blockIdx.x * BM;
    const int n0   = blockIdx.y * BN;
    const int tid  = threadIdx.x;
    const int warp = tid >> 5;
    const int wm   = warp & 3;
    const int wn   = warp >> 2;

    // Per-pair active flags (block-uniform; derived from small NAS reads)
    int nas_eff[6];
    #pragma unroll
    for (int f = 0; f < 6; f++) nas_eff[f] = (f < 2) ? 1 : NAS[f];

    wmma::fragment<wmma::accumulator, 16, 16, 8, float> cf[2][2];
    #pragma unroll
    for (int a = 0; a < 2; a++)
        #pragma unroll
        for (int b = 0; b < 2; b++)
            wmma::fill_fragment(cf[a][b], 0.0f);

    for (int k0 = 0; k0 < KFINAL; k0 += BK) {
        const int p = k0 >> 8;                       // pair owning this K-tile
        if (nas_eff[c_PI[p]] * nas_eff[c_PJ[p]] == 0) continue;  // block-uniform skip

        const float* Asrc = g_H + ((size_t)p * TOKENS + tok0) * EMBED + (k0 & (EMBED - 1));

        #pragma unroll
        for (int t = 0; t < 4; t++) {
            int q   = tid + t * NTHREADS;
            int row = q >> 3, c4 = q & 7;
            float4 v = *reinterpret_cast<const float4*>(Asrc + (size_t)row * EMBED + c4 * 4);
            float* d = As + row * LDA + c4 * 4;
            d[0] = wmma::__float_to_tf32(v.x);
            d[1] = wmma::__float_to_tf32(v.y);
            d[2] = wmma::__float_to_tf32(v.z);
            d[3] = wmma::__float_to_tf32(v.w);
        }
        #pragma unroll
        for (int t = 0; t < 2; t++) {
            int q   = tid + t * NTHREADS;
            int row = q >> 4, c4 = q & 15;
            float4 v = *reinterpret_cast<const float4*>(
                W_final + (size_t)(k0 + row) * EMBED + n0 + c4 * 4);
            float* d = Bs + row * LDB + c4 * 4;
            d[0] = wmma::__float_to_tf32(v.x);
            d[1] = wmma::__float_to_tf32(v.y);
            d[2] = wmma::__float_to_tf32(v.z);
            d[3] = wmma::__float_to_tf32(v.w);
        }
        __syncthreads();

        #pragma unroll
        for (int kk = 0; kk < BK; kk += 8) {
            wmma::fragment<wmma::matrix_a, 16, 16, 8, wmma::precision::tf32, wmma::row_major> af[2];
            wmma::fragment<wmma::matrix_b, 16, 16, 8, wmma::precision::tf32, wmma::row_major> bf[2];
            wmma::load_matrix_sync(af[0], As + (wm * 32 +  0) * LDA + kk, LDA);
            wmma::load_matrix_sync(af[1], As + (wm * 32 + 16) * LDA + kk, LDA);
            wmma::load_matrix_sync(bf[0], Bs + kk * LDB + wn * 32 +  0, LDB);
            wmma::load_matrix_sync(bf[1], Bs + kk * LDB + wn * 32 + 16, LDB);
            #pragma unroll
            for (int a = 0; a < 2; a++)
                #pragma unroll
                for (int b = 0; b < 2; b++)
                    wmma::mma_sync(cf[a][b], af[a], bf[b], cf[a][b]);
        }
        __syncthreads();
    }

    #pragma unroll
    for (int a = 0; a < 2; a++)
        #pragma unroll
        for (int b = 0; b < 2; b++)
            wmma::store_matrix_sync(smem + (wm * 32 + a * 16) * BN + wn * 32 + b * 16,
                                    cf[a][b], BN, wmma::mem_row_major);
    __syncthreads();

    const float* bf_ = b_final + n0;
    float* Optr = out + (size_t)tok0 * EMBED + n0;
    for (int q = tid; q < BM * BN / 4; q += NTHREADS) {
        int row = q >> 4, c4 = q & 15;
        float4 v  = *reinterpret_cast<float4*>(smem + row * BN + c4 * 4);
        float4 bb = *reinterpret_cast<const float4*>(bf_ + c4 * 4);
        float4 o;
        o.x = v.x + bb.x;
        o.y = v.y + bb.y;
        o.z = v.z + bb.z;
        o.w = v.w + bb.w;
        *reinterpret_cast<float4*>(Optr + (size_t)row * EMBED + c4 * 4) = o;
    }
}

// ---------------------------------------------------------------------------
extern "C" void kernel_launch(void* const* d_in, const int* in_sizes, int n_in,
                              void* d_out, int out_size)
{
    const float* features = (const float*)d_in[0];
    const float* W_pair   = (const float*)d_in[1];
    const float* b_pair   = (const float*)d_in[2];
    const float* W_final  = (const float*)d_in[3];
    const float* b_final  = (const float*)d_in[4];
    const int*   NAS      = (const int*)  d_in[5];
    float*       out      = (float*)d_out;

    dim3 block(NTHREADS);
    dim3 grid1(TOKENS / BM, EMBED / BN, PAIRS);   // 128 x 4 x 15
    pair_gemm_kernel<<<grid1, block>>>(features, W_pair, b_pair, NAS);

    dim3 grid2(TOKENS / BM, EMBED / BN);          // 128 x 4
    final_gemm_kernel<<<grid2, block>>>(W_final, b_final, NAS, out);
}

// round 7
// speedup vs baseline: 1.2062x; 1.1933x over previous
#include <cuda_runtime.h>
#include <mma.h>
#include <math.h>

using namespace nvcuda;

#define EMBED   256
#define PAIRS   15
#define TOKENS  16384            // 32 * 512
#define KPAIR   512              // 2 * EMBED
#define KFINAL  (PAIRS * EMBED)  // 3840

#define BM 128
#define BN 128
#define BK 16
#define LDA 20                   // 16 + 4 pad (80B rows, 16B-aligned)
#define LDB 132                  // 128 + 4 pad (528B rows, 16B-aligned)
#define LDC 132
#define NTHREADS 256

#define A_STAGE (BM * LDA)       // 2560 floats
#define B_STAGE (BK * LDB)       // 2112 floats
#define SMEM_FLOATS (2 * A_STAGE + 2 * B_STAGE)  // 9344 floats = 37376 B (< 48KB static)

// Intermediate H[p][token][d] (fp32). ~252 MB static device array (allocation-free).
__device__ float g_H[(size_t)PAIRS * TOKENS * EMBED];

// triu_indices(6, k=1) order
__constant__ int c_PI[PAIRS] = {0,0,0,0,0,1,1,1,1,2,2,2,3,3,4};
__constant__ int c_PJ[PAIRS] = {1,2,3,4,5,2,3,4,5,3,4,5,4,5,5};

#define CVT4(dst, v)                                   \
    do {                                               \
        (dst)[0] = wmma::__float_to_tf32((v).x);       \
        (dst)[1] = wmma::__float_to_tf32((v).y);       \
        (dst)[2] = wmma::__float_to_tf32((v).z);       \
        (dst)[3] = wmma::__float_to_tf32((v).w);       \
    } while (0)

// ---------------------------------------------------------------------------
// Kernel 1: H[p] = tanh(concat(F_i, F_j) @ W_pair[p] + b_pair[p])  (active pairs)
// CTA 128x128, 8 warps (2 in M x 4 in N), warp tile 64x32 = 4x2 m16n16k8 tf32.
// BK=16, double-buffered smem + register prefetch: 1 syncthreads per K-iter.
// ---------------------------------------------------------------------------
__global__ void __launch_bounds__(NTHREADS, 2)
pair_gemm_kernel(const float* __restrict__ features,
                 const float* __restrict__ W_pair,
                 const float* __restrict__ b_pair,
                 const int*   __restrict__ NAS)
{
    __shared__ float smem[SMEM_FLOATS];

    const int p  = blockIdx.z;
    const int fi = c_PI[p], fj = c_PJ[p];
    const int ni = (fi < 2) ? 1 : NAS[fi];
    const int nj = (fj < 2) ? 1 : NAS[fj];
    if (ni * nj == 0) return;          // inactive pair: kernel 2 never reads this region

    const int tok0 = blockIdx.x * BM;
    const int n0   = blockIdx.y * BN;
    const int tid  = threadIdx.x;
    const int warp = tid >> 5;
    const int wm   = warp & 1;         // 0..1  (64-row half)
    const int wn   = warp >> 1;        // 0..3  (32-col slice)

    const float* featI = features + ((size_t)fi * TOKENS + tok0) * EMBED;
    const float* featJ = features + ((size_t)fj * TOKENS + tok0) * EMBED;
    const float* Wp    = W_pair   + (size_t)p * KPAIR * EMBED + n0;

    // per-thread load coordinates
    const int arow = tid >> 2,  ac4 = (tid & 3)  * 4;   // A: rows arow, arow+64
    const int brow = tid >> 5,  bc4 = (tid & 31) * 4;   // B: rows brow, brow+8

    // prologue: stage 0 <- k-tile 0
    {
        #pragma unroll
        for (int t = 0; t < 2; t++) {
            int r = arow + t * 64;
            float4 v = *(const float4*)(featI + (size_t)r * EMBED + ac4);
            CVT4(smem + r * LDA + ac4, v);
        }
        #pragma unroll
        for (int t = 0; t < 2; t++) {
            int r = brow + t * 8;
            float4 v = *(const float4*)(Wp + (size_t)r * EMBED + bc4);
            CVT4(smem + 2 * A_STAGE + r * LDB + bc4, v);
        }
    }
    __syncthreads();

    wmma::fragment<wmma::accumulator, 16, 16, 8, float> cf[4][2];
    #pragma unroll
    for (int a = 0; a < 4; a++)
        #pragma unroll
        for (int b = 0; b < 2; b++)
            wmma::fill_fragment(cf[a][b], 0.0f);

    const int NK = KPAIR / BK;   // 32
    int buf = 0;
    for (int it = 0; it < NK; it++) {
        float4 aR[2], bR[2];
        const bool havenext = (it + 1 < NK);
        if (havenext) {
            const int k0 = (it + 1) * BK;
            const float* Asrc = (k0 < EMBED) ? (featI + k0) : (featJ + (k0 - EMBED));
            #pragma unroll
            for (int t = 0; t < 2; t++)
                aR[t] = *(const float4*)(Asrc + (size_t)(arow + t * 64) * EMBED + ac4);
            #pragma unroll
            for (int t = 0; t < 2; t++)
                bR[t] = *(const float4*)(Wp + (size_t)(k0 + brow + t * 8) * EMBED + bc4);
        }

        const float* Ab = smem + buf * A_STAGE + wm * 64 * LDA;
        const float* Bb = smem + 2 * A_STAGE + buf * B_STAGE + wn * 32;
        #pragma unroll
        for (int kk = 0; kk < BK; kk += 8) {
            wmma::fragment<wmma::matrix_a, 16, 16, 8, wmma::precision::tf32, wmma::row_major> af[4];
            wmma::fragment<wmma::matrix_b, 16, 16, 8, wmma::precision::tf32, wmma::row_major> bf[2];
            #pragma unroll
            for (int a = 0; a < 4; a++)
                wmma::load_matrix_sync(af[a], Ab + (a * 16) * LDA + kk, LDA);
            #pragma unroll
            for (int b = 0; b < 2; b++)
                wmma::load_matrix_sync(bf[b], Bb + kk * LDB + b * 16, LDB);
            #pragma unroll
            for (int a = 0; a < 4; a++)
                #pragma unroll
                for (int b = 0; b < 2; b++)
                    wmma::mma_sync(cf[a][b], af[a], bf[b], cf[a][b]);
        }

        if (havenext) {
            const int nb = buf ^ 1;
            #pragma unroll
            for (int t = 0; t < 2; t++)
                CVT4(smem + nb * A_STAGE + (arow + t * 64) * LDA + ac4, aR[t]);
            #pragma unroll
            for (int t = 0; t < 2; t++)
                CVT4(smem + 2 * A_STAGE + nb * B_STAGE + (brow + t * 8) * LDB + bc4, bR[t]);
        }
        __syncthreads();
        buf ^= 1;
    }

    // epilogue: stage C through smem in two 64-row halves, bias + tanh, coalesced writes
    float*       Hout = g_H    + ((size_t)p * TOKENS + tok0) * EMBED + n0;
    const float* bp   = b_pair + p * EMBED + n0;
    float* Cs = smem;   // 64*132 = 8448 floats, fits
    #pragma unroll
    for (int half = 0; half < 2; half++) {
        if (wm == half) {
            #pragma unroll
            for (int a = 0; a < 4; a++)
                #pragma unroll
                for (int b = 0; b < 2; b++)
                    wmma::store_matrix_sync(Cs + (a * 16) * LDC + wn * 32 + b * 16,
                                            cf[a][b], LDC, wmma::mem_row_major);
        }
        __syncthreads();
        #pragma unroll
        for (int t = 0; t < 8; t++) {
            int q   = tid + t * NTHREADS;      // 64 rows x 32 float4
            int row = q >> 5, c4 = (q & 31) * 4;
            float4 v  = *(float4*)(Cs + row * LDC + c4);
            float4 bb = *(const float4*)(bp + c4);
            float4 o;
            o.x = tanhf(v.x + bb.x);
            o.y = tanhf(v.y + bb.y);
            o.z = tanhf(v.z + bb.z);
            o.w = tanhf(v.w + bb.w);
            *(float4*)(Hout + (size_t)(half * 64 + row) * EMBED + c4) = o;
        }
        __syncthreads();
    }
}

// ---------------------------------------------------------------------------
// Kernel 2: out = H_flat @ W_final + b_final, skipping inactive pairs' K-tiles.
// Same pipelined 128x128 scheme; K-iteration space = dense list of active tiles.
// ---------------------------------------------------------------------------
__global__ void __launch_bounds__(NTHREADS, 2)
final_gemm_kernel(const float* __restrict__ W_final,
                  const float* __restrict__ b_final,
                  const int*   __restrict__ NAS,
                  float*       __restrict__ out)
{
    __shared__ float smem[SMEM_FLOATS];

    const int tok0 = blockIdx.x * BM;
    const int n0   = blockIdx.y * BN;
    const int tid  = threadIdx.x;
    const int warp = tid >> 5;
    const int wm   = warp & 1;
    const int wn   = warp >> 1;

    int nas_eff[6];
    #pragma unroll
    for (int f = 0; f < 6; f++) nas_eff[f] = (f < 2) ? 1 : NAS[f];
    int plist[PAIRS]; int np = 0;
    #pragma unroll
    for (int p = 0; p < PAIRS; p++)
        if (nas_eff[c_PI[p]] * nas_eff[c_PJ[p]] != 0) plist[np++] = p;
    const int TPP = EMBED / BK;        // 16 tiles per pair
    const int NK  = np * TPP;          // >= 16 (pair (0,1) always active)

    const int arow = tid >> 2,  ac4 = (tid & 3)  * 4;
    const int brow = tid >> 5,  bc4 = (tid & 31) * 4;

    // prologue: stage 0 <- first active tile
    {
        const int p0 = plist[0];
        const float* Asrc = g_H + ((size_t)p0 * TOKENS + tok0) * EMBED;
        const int kg = p0 * EMBED;     // global K row of W_final
        #pragma unroll
        for (int t = 0; t < 2; t++) {
            int r = arow + t * 64;
            float4 v = *(const float4*)(Asrc + (size_t)r * EMBED + ac4);
            CVT4(smem + r * LDA + ac4, v);
        }
        #pragma unroll
        for (int t = 0; t < 2; t++) {
            int r = brow + t * 8;
            float4 v = *(const float4*)(W_final + (size_t)(kg + r) * EMBED + n0 + bc4);
            CVT4(smem + 2 * A_STAGE + r * LDB + bc4, v);
        }
    }
    __syncthreads();

    wmma::fragment<wmma::accumulator, 16, 16, 8, float> cf[4][2];
    #pragma unroll
    for (int a = 0; a < 4; a++)
        #pragma unroll
        for (int b = 0; b < 2; b++)
            wmma::fill_fragment(cf[a][b], 0.0f);

    int buf = 0;
    for (int it = 0; it < NK; it++) {
        float4 aR[2], bR[2];
        const bool havenext = (it + 1 < NK);
        if (havenext) {
            const int jt   = it + 1;
            const int pn   = plist[jt >> 4];         // TPP == 16
            const int koff = (jt & 15) * BK;
            const float* Asrc = g_H + ((size_t)pn * TOKENS + tok0) * EMBED + koff;
            const int kg = pn * EMBED + koff;
            #pragma unroll
            for (int t = 0; t < 2; t++)
                aR[t] = *(const float4*)(Asrc + (size_t)(arow + t * 64) * EMBED + ac4);
            #pragma unroll
            for (int t = 0; t < 2; t++)
                bR[t] = *(const float4*)(W_final + (size_t)(kg + brow + t * 8) * EMBED + n0 + bc4);
        }

        const float* Ab = smem + buf * A_STAGE + wm * 64 * LDA;
        const float* Bb = smem + 2 * A_STAGE + buf * B_STAGE + wn * 32;
        #pragma unroll
        for (int kk = 0; kk < BK; kk += 8) {
            wmma::fragment<wmma::matrix_a, 16, 16, 8, wmma::precision::tf32, wmma::row_major> af[4];
            wmma::fragment<wmma::matrix_b, 16, 16, 8, wmma::precision::tf32, wmma::row_major> bf[2];
            #pragma unroll
            for (int a = 0; a < 4; a++)
                wmma::load_matrix_sync(af[a], Ab + (a * 16) * LDA + kk, LDA);
            #pragma unroll
            for (int b = 0; b < 2; b++)
                wmma::load_matrix_sync(bf[b], Bb + kk * LDB + b * 16, LDB);
            #pragma unroll
            for (int a = 0; a < 4; a++)
                #pragma unroll
                for (int b = 0; b < 2; b++)
                    wmma::mma_sync(cf[a][b], af[a], bf[b], cf[a][b]);
        }

        if (havenext) {
            const int nb = buf ^ 1;
            #pragma unroll
            for (int t = 0; t < 2; t++)
                CVT4(smem + nb * A_STAGE + (arow + t * 64) * LDA + ac4, aR[t]);
            #pragma unroll
            for (int t = 0; t < 2; t++)
                CVT4(smem + 2 * A_STAGE + nb * B_STAGE + (brow + t * 8) * LDB + bc4, bR[t]);
        }
        __syncthreads();
        buf ^= 1;
    }

    // epilogue: bias only
    float*       Optr = out     + (size_t)tok0 * EMBED + n0;
    const float* bf_  = b_final + n0;
    float* Cs = smem;
    #pragma unroll
    for (int half = 0; half < 2; half++) {
        if (wm == half) {
            #pragma unroll
            for (int a = 0; a < 4; a++)
                #pragma unroll
                for (int b = 0; b < 2; b++)
                    wmma::store_matrix_sync(Cs + (a * 16) * LDC + wn * 32 + b * 16,
                                            cf[a][b], LDC, wmma::mem_row_major);
        }
        __syncthreads();
        #pragma unroll
        for (int t = 0; t < 8; t++) {
            int q   = tid + t * NTHREADS;
            int row = q >> 5, c4 = (q & 31) * 4;
            float4 v  = *(float4*)(Cs + row * LDC + c4);
            float4 bb = *(const float4*)(bf_ + c4);
            float4 o;
            o.x = v.x + bb.x;
            o.y = v.y + bb.y;
            o.z = v.z + bb.z;
            o.w = v.w + bb.w;
            *(float4*)(Optr + (size_t)(half * 64 + row) * EMBED + c4) = o;
        }
        __syncthreads();
    }
}

// ---------------------------------------------------------------------------
extern "C" void kernel_launch(void* const* d_in, const int* in_sizes, int n_in,
                              void* d_out, int out_size)
{
    const float* features = (const float*)d_in[0];
    const float* W_pair   = (const float*)d_in[1];
    const float* b_pair   = (const float*)d_in[2];
    const float* W_final  = (const float*)d_in[3];
    const float* b_final  = (const float*)d_in[4];
    const int*   NAS      = (const int*)  d_in[5];
    float*       out      = (float*)d_out;

    dim3 block(NTHREADS);
    dim3 grid1(TOKENS / BM, EMBED / BN, PAIRS);   // 128 x 2 x 15
    pair_gemm_kernel<<<grid1, block>>>(features, W_pair, b_pair, NAS);

    dim3 grid2(TOKENS / BM, EMBED / BN);          // 128 x 2
    final_gemm_kernel<<<grid2, block>>>(W_final, b_final, NAS, out);
}